// round 10
// baseline (speedup 1.0000x reference)
#include <cuda_runtime.h>
#include <cstdint>

// EmbeddingLSQ: out[t, d] = (idx[t]==0) ? 0 : round(clamp(W[d, idx[t]]/a, -8, 7))*a
// where idx[t] = argmax_v x[t, v]  (x is one-hot float32).
//
// Pipeline (2 kernels):
//  K1 find_idx : early-exit scan (batch-2, MLP=2 — R8's measured optimum)
//                -> g_idx[] + fused histogram; the LAST block to finish runs
//                the counting sort (scan 2000 buckets + smem-offset scatter)
//                inline and resets all cross-call state.
//  K2 gather   : warp-coalesced gather of W columns over sorted tokens,
//                smem transpose, coalesced output writes.
//
// Cross-call state (g_cnt, g_done) is zero at entry of every call: zero-init
// on first call, re-zeroed by the sorting block each call -> graph replays
// do identical work.

#define VOCAB    32000
#define DIM      1024
#define TOKENS   4096
#define NTHREADS 256
#define U4_PER_ROW (VOCAB / 4)          // 8000 uint4 per row
#define NBUCKETS (VOCAB / 16)           // 2000, each spans 64B of a W row
#define GROUP    32                     // tokens per gather group

__device__ int g_idx[TOKENS];
__device__ int g_cnt[NBUCKETS];         // zero at entry of every call
__device__ int g_done;                  // zero at entry of every call
__device__ int g_order[TOKENS];
__device__ int g_sidx[TOKENS];

// ---------------- K1: early-exit scan + fused histogram + last-block sort ----------------
__global__ __launch_bounds__(NTHREADS, 8)
void find_idx_kernel(const float* __restrict__ x) {
    const int t = blockIdx.x;
    __shared__ int s_idx;
    __shared__ int s_found;
    if (threadIdx.x == 0) { s_found = 0; s_idx = 0; }
    __syncthreads();

    const uint4* __restrict__ row =
        reinterpret_cast<const uint4*>(x + (size_t)t * VOCAB);
    volatile int* vflag = &s_found;

    // Batch of 2 independent LDG.128 per flag poll (R8 optimum: MLP=2,
    // no wasted prefetch batch).
    for (int base = 0; base < 32; base += 2) {
        if (*vflag) break;
        const int j0 = threadIdx.x + base * NTHREADS;
        const int j1 = j0 + NTHREADS;
        const bool p0 = (j0 < U4_PER_ROW);
        const bool p1 = (j1 < U4_PER_ROW);
        uint4 v0, v1;
        if (p0) v0 = row[j0];
        if (p1) v1 = row[j1];
        if (p0 && (v0.x | v0.y | v0.z | v0.w)) {
            s_idx = j0 * 4 + (v0.x ? 0 : (v0.y ? 1 : (v0.z ? 2 : 3)));
            __threadfence_block();
            *vflag = 1;
        }
        if (p1 && (v1.x | v1.y | v1.z | v1.w)) {
            s_idx = j1 * 4 + (v1.x ? 0 : (v1.y ? 1 : (v1.z ? 2 : 3)));
            __threadfence_block();
            *vflag = 1;
        }
    }
    __syncthreads();   // rendezvous: finder's s_idx visible to thread 0

    __shared__ int s_last;
    if (threadIdx.x == 0) {
        const int idx = s_idx;
        g_idx[t] = idx;
        atomicAdd(&g_cnt[idx >> 4], 1);    // fused histogram
        __threadfence();                   // publish g_idx/g_cnt before counter
        const int done = atomicAdd(&g_done, 1);
        s_last = (done == gridDim.x - 1);
    }
    __syncthreads();
    if (!s_last) return;

    // ---- last block: counting sort (scan + scatter), 256 threads ----
    __shared__ int bufA[2048], bufB[2048];
    const int tid = threadIdx.x;

    for (int i = tid; i < 2048; i += NTHREADS) {
        int c = 0;
        if (i < NBUCKETS) { c = g_cnt[i]; g_cnt[i] = 0; }   // re-zero for next call
        bufA[i] = c;
    }
    __syncthreads();

    int* src = bufA; int* dst = bufB;
    for (int d = 1; d < 2048; d <<= 1) {
        for (int i = tid; i < 2048; i += NTHREADS)
            dst[i] = (i >= d) ? (src[i] + src[i - d]) : src[i];
        __syncthreads();
        int* tmp = src; src = dst; dst = tmp;
    }
    for (int i = tid; i < 2048; i += NTHREADS)
        dst[i] = (i == 0) ? 0 : src[i - 1];
    __syncthreads();

    for (int k = 0; k < TOKENS / NTHREADS; k++) {
        const int tt  = tid + k * NTHREADS;
        const int idx = g_idx[tt];
        const int pos = atomicAdd(&dst[idx >> 4], 1);
        g_order[pos] = tt;
        g_sidx[pos]  = idx;
    }
    __syncthreads();
    if (tid == 0) g_done = 0;              // reset for next call / replay
}

// ---------------- K2: warp-coalesced gather + LSQ + transpose write ----------------
// grid = (TOKENS/GROUP, DIM/128); block = 256 (8 warps).
__global__ __launch_bounds__(NTHREADS)
void gather_lsq_kernel(const float* __restrict__ w,
                       const float* __restrict__ alpha,
                       float* __restrict__ out) {
    __shared__ int   s_tok[GROUP];
    __shared__ int   s_ix[GROUP];
    __shared__ float tile[32][33];

    const int tid  = threadIdx.x;
    const int warp = tid >> 5;
    const int lane = tid & 31;
    const int gbase  = blockIdx.x * GROUP;
    const int dbase0 = blockIdx.y * 128;

    if (tid < GROUP) {
        s_tok[tid] = g_order[gbase + tid];
        s_ix[tid]  = g_sidx[gbase + tid];
    }
    __syncthreads();

    const float a = __ldg(alpha);
    const int   myidx = s_ix[lane];        // lane <-> sorted token (load phase)
    const bool  pad   = (myidx == 0);

    #pragma unroll
    for (int c = 0; c < 4; c++) {
        const int dbase = dbase0 + c * 32;
        float wv[4];
        #pragma unroll
        for (int r = 0; r < 4; r++)
            wv[r] = __ldg(w + (size_t)(dbase + warp * 4 + r) * VOCAB + myidx);
        #pragma unroll
        for (int r = 0; r < 4; r++) {
            float q = pad ? 0.0f
                          : rintf(fminf(fmaxf(wv[r] / a, -8.0f), 7.0f)) * a;
            tile[warp * 4 + r][lane] = q;
        }
        __syncthreads();
        #pragma unroll
        for (int r = 0; r < 4; r++) {
            const int tl = warp * 4 + r;
            const int t  = s_tok[tl];
            out[(size_t)t * DIM + dbase + lane] = tile[lane][tl];
        }
        __syncthreads();
    }
}

extern "C" void kernel_launch(void* const* d_in, const int* in_sizes, int n_in,
                              void* d_out, int out_size) {
    const float* x     = (const float*)d_in[0];
    const float* w     = (const float*)d_in[1];
    const float* alpha = (const float*)d_in[2];
    float* out = (float*)d_out;

    find_idx_kernel<<<TOKENS, NTHREADS>>>(x);
    dim3 grid(TOKENS / GROUP, DIM / 128);
    gather_lsq_kernel<<<grid, NTHREADS>>>(w, alpha, out);
}

// round 11
// speedup vs baseline: 1.0352x; 1.0352x over previous
#include <cuda_runtime.h>
#include <cstdint>

// EmbeddingLSQ: out[t, d] = (idx[t]==0) ? 0 : round(clamp(W[d, idx[t]]/a, -8, 7))*a
// where idx[t] = argmax_v x[t, v]  (x is one-hot float32).
//
// Pipeline (2 kernels):
//  K1 find_idx : early-exit scan (batch-2, MLP=2 — measured optimum R8)
//                -> g_idx[] + fused bucket histogram. Also resets g_sort_done
//                for this call (ordered before K2 by the kernel boundary).
//  K2 gather   : block (0,0) runs the counting sort at its head (hierarchical
//                scan of 2000 bucket counts + smem-offset scatter), sets
//                g_sort_done; the other 1023 blocks (all resident in wave 1)
//                spin on the flag, then everyone gathers. Gather loop is
//                software-pipelined (chunk c+1 loads issued before chunk c's
//                transpose/writes).
//
// Cross-call state: g_cnt zero at entry (zero-init first call, re-zeroed by the
// sort block each call). g_sort_done reset by K1 each call. Replays identical.

#define VOCAB    32000
#define DIM      1024
#define TOKENS   4096
#define NTHREADS 256
#define U4_PER_ROW (VOCAB / 4)          // 8000 uint4 per row
#define NBUCKETS 2000                   // idx>>4 buckets (64B vocab span)
#define NBUCKPAD 2048
#define GROUP    32                     // tokens per gather group

__device__ int g_idx[TOKENS];
__device__ __align__(16) int g_cnt[NBUCKPAD];   // zero at entry of every call
__device__ int g_sort_done;                     // reset by K1 every call
__device__ int g_order[TOKENS];
__device__ int g_sidx[TOKENS];

// ---------------- K1: early-exit scan + fused histogram ----------------
__global__ __launch_bounds__(NTHREADS, 8)
void find_idx_kernel(const float* __restrict__ x) {
    const int t = blockIdx.x;
    if (t == 0 && threadIdx.x == 0) g_sort_done = 0;   // ordered before K2

    __shared__ int s_idx;
    __shared__ int s_found;
    if (threadIdx.x == 0) { s_found = 0; s_idx = 0; }
    __syncthreads();

    const uint4* __restrict__ row =
        reinterpret_cast<const uint4*>(x + (size_t)t * VOCAB);
    volatile int* vflag = &s_found;

    // Batch of 2 independent LDG.128 per flag poll (MLP=2, no wasted prefetch).
    for (int base = 0; base < 32; base += 2) {
        if (*vflag) break;
        const int j0 = threadIdx.x + base * NTHREADS;
        const int j1 = j0 + NTHREADS;
        const bool p0 = (j0 < U4_PER_ROW);
        const bool p1 = (j1 < U4_PER_ROW);
        uint4 v0, v1;
        if (p0) v0 = row[j0];
        if (p1) v1 = row[j1];
        if (p0 && (v0.x | v0.y | v0.z | v0.w)) {
            s_idx = j0 * 4 + (v0.x ? 0 : (v0.y ? 1 : (v0.z ? 2 : 3)));
            __threadfence_block();
            *vflag = 1;
        }
        if (p1 && (v1.x | v1.y | v1.z | v1.w)) {
            s_idx = j1 * 4 + (v1.x ? 0 : (v1.y ? 1 : (v1.z ? 2 : 3)));
            __threadfence_block();
            *vflag = 1;
        }
    }
    __syncthreads();   // rendezvous: finder's s_idx visible to thread 0
    if (threadIdx.x == 0) {
        const int idx = s_idx;
        g_idx[t] = idx;
        atomicAdd(&g_cnt[idx >> 4], 1);    // fused histogram
    }
}

// ---------------- K2: embedded sort (block 0) + warp-coalesced gather ----------------
// grid = (TOKENS/GROUP=128, DIM/128=8) = 1024 blocks; block = 256 (8 warps).
// All 1024 blocks are resident in wave 1 (capacity 148*8=1184) -> spin is safe.
__global__ __launch_bounds__(NTHREADS, 8)
void gather_lsq_kernel(const float* __restrict__ w,
                       const float* __restrict__ alpha,
                       float* __restrict__ out) {
    __shared__ int   s_tok[GROUP];
    __shared__ int   s_ix[GROUP];
    __shared__ float tile[32][33];

    const int tid  = threadIdx.x;
    const int warp = tid >> 5;
    const int lane = tid & 31;

    if (blockIdx.x == 0 && blockIdx.y == 0) {
        // ---- counting sort: hierarchical scan + scatter ----
        __shared__ int s_off[NBUCKPAD];
        __shared__ int s_wsum[8];
        __shared__ int s_wbase[8];

        // load 8 counts/thread (int4 x2), zero g_cnt for next call
        const int b8 = tid * 8;
        int4 ca = *reinterpret_cast<const int4*>(&g_cnt[b8]);
        int4 cb = *reinterpret_cast<const int4*>(&g_cnt[b8 + 4]);
        const int4 z4 = make_int4(0, 0, 0, 0);
        *reinterpret_cast<int4*>(&g_cnt[b8])     = z4;
        *reinterpret_cast<int4*>(&g_cnt[b8 + 4]) = z4;

        int v[8] = {ca.x, ca.y, ca.z, ca.w, cb.x, cb.y, cb.z, cb.w};
        #pragma unroll
        for (int k = 1; k < 8; k++) v[k] += v[k - 1];    // inclusive, serial
        const int tsum = v[7];
        int incl = tsum;                                  // warp inclusive scan
        #pragma unroll
        for (int o = 1; o < 32; o <<= 1) {
            int n = __shfl_up_sync(0xffffffffu, incl, o);
            if (lane >= o) incl += n;
        }
        if (lane == 31) s_wsum[warp] = incl;
        __syncthreads();
        if (tid == 0) {
            int acc = 0;
            #pragma unroll
            for (int i = 0; i < 8; i++) { s_wbase[i] = acc; acc += s_wsum[i]; }
        }
        __syncthreads();
        const int tbase = s_wbase[warp] + (incl - tsum);  // excl base, 8 buckets
        #pragma unroll
        for (int k = 0; k < 8; k++)
            s_off[b8 + k] = tbase + (k == 0 ? 0 : v[k - 1]);
        __syncthreads();

        // scatter 4096 tokens via smem atomics
        #pragma unroll
        for (int k = 0; k < TOKENS / NTHREADS; k++) {
            const int tt  = tid + k * NTHREADS;
            const int idx = g_idx[tt];
            const int pos = atomicAdd(&s_off[idx >> 4], 1);
            g_order[pos] = tt;
            g_sidx[pos]  = idx;
        }
        __syncthreads();
        if (tid == 0) {
            __threadfence();               // publish g_order/g_sidx
            *(volatile int*)&g_sort_done = 1;
        }
    } else {
        if (tid == 0) {
            volatile int* f = &g_sort_done;
            while (*f == 0) __nanosleep(128);
        }
        __syncthreads();
    }

    // ---- gather ----
    const int gbase  = blockIdx.x * GROUP;
    const int dbase0 = blockIdx.y * 128;

    if (tid < GROUP) {
        s_tok[tid] = g_order[gbase + tid];
        s_ix[tid]  = g_sidx[gbase + tid];
    }
    __syncthreads();

    const float a = __ldg(alpha);
    const int   myidx = s_ix[lane];        // lane <-> sorted token (load phase)
    const bool  pad   = (myidx == 0);

    // software-pipelined over 4 chunks of 32 d: chunk c+1 loads issued
    // before chunk c's transpose/writes (LDGs ride across BAR.SYNC).
    float wv[4];
    #pragma unroll
    for (int r = 0; r < 4; r++)
        wv[r] = __ldg(w + (size_t)(dbase0 + warp * 4 + r) * VOCAB + myidx);

    #pragma unroll
    for (int c = 0; c < 4; c++) {
        float nv[4];
        if (c < 3) {
            const int dnext = dbase0 + (c + 1) * 32;
            #pragma unroll
            for (int r = 0; r < 4; r++)
                nv[r] = __ldg(w + (size_t)(dnext + warp * 4 + r) * VOCAB + myidx);
        }
        const int dbase = dbase0 + c * 32;
        #pragma unroll
        for (int r = 0; r < 4; r++) {
            float q = pad ? 0.0f
                          : rintf(fminf(fmaxf(wv[r] / a, -8.0f), 7.0f)) * a;
            tile[warp * 4 + r][lane] = q;
        }
        __syncthreads();
        #pragma unroll
        for (int r = 0; r < 4; r++) {
            const int tl = warp * 4 + r;
            const int t  = s_tok[tl];
            out[(size_t)t * DIM + dbase + lane] = tile[lane][tl];
        }
        __syncthreads();
        #pragma unroll
        for (int r = 0; r < 4; r++) wv[r] = nv[r];
    }
}

extern "C" void kernel_launch(void* const* d_in, const int* in_sizes, int n_in,
                              void* d_out, int out_size) {
    const float* x     = (const float*)d_in[0];
    const float* w     = (const float*)d_in[1];
    const float* alpha = (const float*)d_in[2];
    float* out = (float*)d_out;

    find_idx_kernel<<<TOKENS, NTHREADS>>>(x);
    dim3 grid(TOKENS / GROUP, DIM / 128);
    gather_lsq_kernel<<<grid, NTHREADS>>>(w, alpha, out);
}

// round 12
// speedup vs baseline: 1.0449x; 1.0094x over previous
#include <cuda_runtime.h>
#include <cstdint>

// EmbeddingLSQ: out[t, d] = (idx[t]==0) ? 0 : round(clamp(W[d, idx[t]]/a, -8, 7))*a
// where idx[t] = argmax_v x[t, v]  (x is one-hot float32).
//
// Pipeline (3 kernels — plain launch boundaries; R10/R11 showed fusion tricks lose):
//  K1 find_idx : early-exit scan, batch-4 loads per flag poll (MLP=4)
//                -> g_idx[] + fused bucket histogram (atomicAdd g_cnt)
//  K2 sort     : 1024-thread counting sort, hierarchical scan (warp shfl),
//                re-zeroes g_cnt for the next call.
//  K3 gather   : warp-coalesced gather over sorted tokens, software-pipelined
//                chunks, smem transpose, coalesced writes.
//
// Cross-call state: g_cnt zero at entry every call (zero-init first call,
// re-zeroed by K2) -> graph replays do identical work.

#define VOCAB    32000
#define DIM      1024
#define TOKENS   4096
#define NTHREADS 256
#define U4_PER_ROW (VOCAB / 4)          // 8000 uint4 per row
#define NBUCKETS 2000                   // idx>>4 buckets (64B vocab span)
#define NBUCKPAD 2048
#define GROUP    32                     // tokens per gather group

__device__ int g_idx[TOKENS];
__device__ __align__(16) int g_cnt[NBUCKPAD];   // zero at entry of every call
__device__ int g_order[TOKENS];
__device__ int g_sidx[TOKENS];

// ---------------- K1: early-exit scan (batch-4) + fused histogram ----------------
__global__ __launch_bounds__(NTHREADS, 8)
void find_idx_kernel(const float* __restrict__ x) {
    const int t = blockIdx.x;
    __shared__ int s_idx;
    __shared__ int s_found;
    if (threadIdx.x == 0) { s_found = 0; s_idx = 0; }
    __syncthreads();

    const uint4* __restrict__ row =
        reinterpret_cast<const uint4*>(x + (size_t)t * VOCAB);
    volatile int* vflag = &s_found;

    // 4 independent LDG.128 per flag poll: MLP=4/thread, overshoot ~1 extra
    // iteration vs batch-2 (measured: batch-1 55.7us, batch-2 51.4us).
    for (int base = 0; base < 32; base += 4) {
        if (*vflag) break;
        uint4 v[4];
        bool  p[4];
        #pragma unroll
        for (int i = 0; i < 4; i++) {
            const int j = threadIdx.x + (base + i) * NTHREADS;
            p[i] = (j < U4_PER_ROW);
            if (p[i]) v[i] = row[j];
        }
        #pragma unroll
        for (int i = 0; i < 4; i++) {
            if (p[i] && (v[i].x | v[i].y | v[i].z | v[i].w)) {
                const int j = threadIdx.x + (base + i) * NTHREADS;
                s_idx = j * 4 + (v[i].x ? 0 : (v[i].y ? 1 : (v[i].z ? 2 : 3)));
                __threadfence_block();
                *vflag = 1;     // unique writer (one-hot row)
            }
        }
    }
    __syncthreads();   // rendezvous: finder's s_idx visible to thread 0
    if (threadIdx.x == 0) {
        const int idx = s_idx;
        g_idx[t] = idx;
        atomicAdd(&g_cnt[idx >> 4], 1);    // fused histogram
    }
}

// ---------------- K2: 1024-thread counting sort (hierarchical scan) ----------------
__global__ __launch_bounds__(1024)
void sort_kernel() {
    __shared__ int s_off[NBUCKPAD];
    __shared__ int s_wsum[32];
    const int tid  = threadIdx.x;
    const int warp = tid >> 5;
    const int lane = tid & 31;

    // 2 buckets per thread; load counts + zero for next call
    const int b2 = tid * 2;
    int2 c = *reinterpret_cast<const int2*>(&g_cnt[b2]);
    *reinterpret_cast<int2*>(&g_cnt[b2]) = make_int2(0, 0);

    const int tsum = c.x + c.y;
    int incl = tsum;
    #pragma unroll
    for (int o = 1; o < 32; o <<= 1) {
        int n = __shfl_up_sync(0xffffffffu, incl, o);
        if (lane >= o) incl += n;
    }
    if (lane == 31) s_wsum[warp] = incl;
    __syncthreads();
    if (warp == 0) {                       // scan the 32 warp sums
        int wsv = s_wsum[lane];
        int wincl = wsv;
        #pragma unroll
        for (int o = 1; o < 32; o <<= 1) {
            int n = __shfl_up_sync(0xffffffffu, wincl, o);
            if (lane >= o) wincl += n;
        }
        s_wsum[lane] = wincl - wsv;        // exclusive warp base
    }
    __syncthreads();
    const int tbase = s_wsum[warp] + (incl - tsum);
    s_off[b2]     = tbase;
    s_off[b2 + 1] = tbase + c.x;
    __syncthreads();

    // scatter 4096 tokens via smem atomics (~2 per bucket)
    #pragma unroll
    for (int k = 0; k < TOKENS / 1024; k++) {
        const int tt  = tid + k * 1024;
        const int idx = g_idx[tt];
        const int pos = atomicAdd(&s_off[idx >> 4], 1);
        g_order[pos] = tt;
        g_sidx[pos]  = idx;
    }
}

// ---------------- K3: warp-coalesced pipelined gather + LSQ + transpose ----------------
// grid = (TOKENS/GROUP=128, DIM/128=8); block = 256 (8 warps).
__global__ __launch_bounds__(NTHREADS, 8)
void gather_lsq_kernel(const float* __restrict__ w,
                       const float* __restrict__ alpha,
                       float* __restrict__ out) {
    __shared__ int   s_tok[GROUP];
    __shared__ int   s_ix[GROUP];
    __shared__ float tile[32][33];

    const int tid  = threadIdx.x;
    const int warp = tid >> 5;
    const int lane = tid & 31;
    const int gbase  = blockIdx.x * GROUP;
    const int dbase0 = blockIdx.y * 128;

    if (tid < GROUP) {
        s_tok[tid] = g_order[gbase + tid];
        s_ix[tid]  = g_sidx[gbase + tid];
    }
    __syncthreads();

    const float a = __ldg(alpha);
    const int   myidx = s_ix[lane];        // lane <-> sorted token (load phase)
    const bool  pad   = (myidx == 0);

    // software-pipelined over 4 chunks of 32 d: chunk c+1 loads issued
    // before chunk c's transpose/writes (LDGs ride across BAR.SYNC).
    float wv[4];
    #pragma unroll
    for (int r = 0; r < 4; r++)
        wv[r] = __ldg(w + (size_t)(dbase0 + warp * 4 + r) * VOCAB + myidx);

    #pragma unroll
    for (int c = 0; c < 4; c++) {
        float nv[4];
        if (c < 3) {
            const int dnext = dbase0 + (c + 1) * 32;
            #pragma unroll
            for (int r = 0; r < 4; r++)
                nv[r] = __ldg(w + (size_t)(dnext + warp * 4 + r) * VOCAB + myidx);
        }
        const int dbase = dbase0 + c * 32;
        #pragma unroll
        for (int r = 0; r < 4; r++) {
            float q = pad ? 0.0f
                          : rintf(fminf(fmaxf(wv[r] / a, -8.0f), 7.0f)) * a;
            tile[warp * 4 + r][lane] = q;
        }
        __syncthreads();
        #pragma unroll
        for (int r = 0; r < 4; r++) {
            const int tl = warp * 4 + r;
            const int t  = s_tok[tl];
            out[(size_t)t * DIM + dbase + lane] = tile[lane][tl];
        }
        __syncthreads();
        #pragma unroll
        for (int r = 0; r < 4; r++) wv[r] = nv[r];
    }
}

extern "C" void kernel_launch(void* const* d_in, const int* in_sizes, int n_in,
                              void* d_out, int out_size) {
    const float* x     = (const float*)d_in[0];
    const float* w     = (const float*)d_in[1];
    const float* alpha = (const float*)d_in[2];
    float* out = (float*)d_out;

    find_idx_kernel<<<TOKENS, NTHREADS>>>(x);
    sort_kernel<<<1, 1024>>>();
    dim3 grid(TOKENS / GROUP, DIM / 128);
    gather_lsq_kernel<<<grid, NTHREADS>>>(w, alpha, out);
}

// round 13
// speedup vs baseline: 1.0746x; 1.0283x over previous
#include <cuda_runtime.h>
#include <cstdint>

// EmbeddingLSQ: out[t, d] = (idx[t]==0) ? 0 : round(clamp(W[d, idx[t]]/a, -8, 7))*a
// where idx[t] = argmax_v x[t, v]  (x is one-hot float32).
//
// Pipeline (3 kernels):
//  K1 find_idx : DUAL-ROW early-exit scan. Each block scans 2 rows, batch-2
//                per row interleaved -> 4 loads/thread in flight (batch-4 BW)
//                but only 2 per row (batch-2 overshoot). Fused histogram.
//  K2 sort     : 1024-thread counting sort, hierarchical warp-shfl scan,
//                re-zeroes g_cnt for the next call.
//  K3 gather   : warp-coalesced gather over sorted tokens, software-pipelined
//                chunks, smem transpose, coalesced writes.
//
// Cross-call state: g_cnt zero at entry every call (zero-init first call,
// re-zeroed by K2) -> graph replays do identical work.

#define VOCAB    32000
#define DIM      1024
#define TOKENS   4096
#define NTHREADS 256
#define U4_PER_ROW (VOCAB / 4)          // 8000 uint4 per row
#define NBUCKETS 2000                   // idx>>4 buckets (64B vocab span)
#define NBUCKPAD 2048
#define GROUP    32                     // tokens per gather group

__device__ int g_idx[TOKENS];
__device__ __align__(16) int g_cnt[NBUCKPAD];   // zero at entry of every call
__device__ int g_order[TOKENS];
__device__ int g_sidx[TOKENS];

// ---------------- K1: dual-row early-exit scan + fused histogram ----------------
__global__ __launch_bounds__(NTHREADS)
void find_idx_kernel(const float* __restrict__ x) {
    const int t0 = blockIdx.x * 2;
    __shared__ int s_idx[2];
    __shared__ int s_flag[2];
    if (threadIdx.x < 2) { s_idx[threadIdx.x] = 0; s_flag[threadIdx.x] = 0; }
    __syncthreads();

    const uint4* __restrict__ rowA =
        reinterpret_cast<const uint4*>(x + (size_t)t0 * VOCAB);
    const uint4* __restrict__ rowB =
        reinterpret_cast<const uint4*>(x + (size_t)(t0 + 1) * VOCAB);
    volatile int* vf = s_flag;

    // Per poll: batch-2 loads for each unfinished row, interleaved.
    // MLP/thread = 4, but per-row in-flight = 2 -> batch-2 overshoot.
    for (int base = 0; base < 32; base += 2) {
        const int fA = vf[0];
        const int fB = vf[1];
        if (fA & fB) break;
        const int j0 = threadIdx.x + base * NTHREADS;
        const int j1 = j0 + NTHREADS;
        const bool p0 = (j0 < U4_PER_ROW);
        const bool p1 = (j1 < U4_PER_ROW);
        uint4 a0, a1, b0, b1;
        if (!fA) {                       // block-uniform predicate
            if (p0) a0 = rowA[j0];
            if (p1) a1 = rowA[j1];
        }
        if (!fB) {
            if (p0) b0 = rowB[j0];
            if (p1) b1 = rowB[j1];
        }
        if (!fA) {
            if (p0 && (a0.x | a0.y | a0.z | a0.w)) {
                s_idx[0] = j0 * 4 + (a0.x ? 0 : (a0.y ? 1 : (a0.z ? 2 : 3)));
                vf[0] = 1;               // unique writer (one-hot row)
            }
            if (p1 && (a1.x | a1.y | a1.z | a1.w)) {
                s_idx[0] = j1 * 4 + (a1.x ? 0 : (a1.y ? 1 : (a1.z ? 2 : 3)));
                vf[0] = 1;
            }
        }
        if (!fB) {
            if (p0 && (b0.x | b0.y | b0.z | b0.w)) {
                s_idx[1] = j0 * 4 + (b0.x ? 0 : (b0.y ? 1 : (b0.z ? 2 : 3)));
                vf[1] = 1;
            }
            if (p1 && (b1.x | b1.y | b1.z | b1.w)) {
                s_idx[1] = j1 * 4 + (b1.x ? 0 : (b1.y ? 1 : (b1.z ? 2 : 3)));
                vf[1] = 1;
            }
        }
    }
    __syncthreads();   // BAR drains STS: s_idx visible below
    if (threadIdx.x < 2) {
        const int idx = s_idx[threadIdx.x];
        g_idx[t0 + threadIdx.x] = idx;
        atomicAdd(&g_cnt[idx >> 4], 1);    // fused histogram
    }
}

// ---------------- K2: 1024-thread counting sort (hierarchical scan) ----------------
__global__ __launch_bounds__(1024)
void sort_kernel() {
    __shared__ int s_off[NBUCKPAD];
    __shared__ int s_wsum[32];
    const int tid  = threadIdx.x;
    const int warp = tid >> 5;
    const int lane = tid & 31;

    // 2 buckets per thread; load counts + zero for next call
    const int b2 = tid * 2;
    int2 c = *reinterpret_cast<const int2*>(&g_cnt[b2]);
    *reinterpret_cast<int2*>(&g_cnt[b2]) = make_int2(0, 0);

    const int tsum = c.x + c.y;
    int incl = tsum;
    #pragma unroll
    for (int o = 1; o < 32; o <<= 1) {
        int n = __shfl_up_sync(0xffffffffu, incl, o);
        if (lane >= o) incl += n;
    }
    if (lane == 31) s_wsum[warp] = incl;
    __syncthreads();
    if (warp == 0) {                       // scan the 32 warp sums
        int wsv = s_wsum[lane];
        int wincl = wsv;
        #pragma unroll
        for (int o = 1; o < 32; o <<= 1) {
            int n = __shfl_up_sync(0xffffffffu, wincl, o);
            if (lane >= o) wincl += n;
        }
        s_wsum[lane] = wincl - wsv;        // exclusive warp base
    }
    __syncthreads();
    const int tbase = s_wsum[warp] + (incl - tsum);
    s_off[b2]     = tbase;
    s_off[b2 + 1] = tbase + c.x;
    __syncthreads();

    // scatter 4096 tokens via smem atomics (~2 per bucket)
    #pragma unroll
    for (int k = 0; k < TOKENS / 1024; k++) {
        const int tt  = tid + k * 1024;
        const int idx = g_idx[tt];
        const int pos = atomicAdd(&s_off[idx >> 4], 1);
        g_order[pos] = tt;
        g_sidx[pos]  = idx;
    }
}

// ---------------- K3: warp-coalesced pipelined gather + LSQ + transpose ----------------
// grid = (TOKENS/GROUP=128, DIM/128=8); block = 256 (8 warps).
__global__ __launch_bounds__(NTHREADS, 8)
void gather_lsq_kernel(const float* __restrict__ w,
                       const float* __restrict__ alpha,
                       float* __restrict__ out) {
    __shared__ int   s_tok[GROUP];
    __shared__ int   s_ix[GROUP];
    __shared__ float tile[32][33];

    const int tid  = threadIdx.x;
    const int warp = tid >> 5;
    const int lane = tid & 31;
    const int gbase  = blockIdx.x * GROUP;
    const int dbase0 = blockIdx.y * 128;

    if (tid < GROUP) {
        s_tok[tid] = g_order[gbase + tid];
        s_ix[tid]  = g_sidx[gbase + tid];
    }
    __syncthreads();

    const float a = __ldg(alpha);
    const int   myidx = s_ix[lane];        // lane <-> sorted token (load phase)
    const bool  pad   = (myidx == 0);

    // software-pipelined over 4 chunks of 32 d: chunk c+1 loads issued
    // before chunk c's transpose/writes (LDGs ride across BAR.SYNC).
    float wv[4];
    #pragma unroll
    for (int r = 0; r < 4; r++)
        wv[r] = __ldg(w + (size_t)(dbase0 + warp * 4 + r) * VOCAB + myidx);

    #pragma unroll
    for (int c = 0; c < 4; c++) {
        float nv[4];
        if (c < 3) {
            const int dnext = dbase0 + (c + 1) * 32;
            #pragma unroll
            for (int r = 0; r < 4; r++)
                nv[r] = __ldg(w + (size_t)(dnext + warp * 4 + r) * VOCAB + myidx);
        }
        const int dbase = dbase0 + c * 32;
        #pragma unroll
        for (int r = 0; r < 4; r++) {
            float q = pad ? 0.0f
                          : rintf(fminf(fmaxf(wv[r] / a, -8.0f), 7.0f)) * a;
            tile[warp * 4 + r][lane] = q;
        }
        __syncthreads();
        #pragma unroll
        for (int r = 0; r < 4; r++) {
            const int tl = warp * 4 + r;
            const int t  = s_tok[tl];
            out[(size_t)t * DIM + dbase + lane] = tile[lane][tl];
        }
        __syncthreads();
        #pragma unroll
        for (int r = 0; r < 4; r++) wv[r] = nv[r];
    }
}

extern "C" void kernel_launch(void* const* d_in, const int* in_sizes, int n_in,
                              void* d_out, int out_size) {
    const float* x     = (const float*)d_in[0];
    const float* w     = (const float*)d_in[1];
    const float* alpha = (const float*)d_in[2];
    float* out = (float*)d_out;

    find_idx_kernel<<<TOKENS / 2, NTHREADS>>>(x);
    sort_kernel<<<1, 1024>>>();
    dim3 grid(TOKENS / GROUP, DIM / 128);
    gather_lsq_kernel<<<grid, NTHREADS>>>(w, alpha, out);
}